// round 6
// baseline (speedup 1.0000x reference)
#include <cuda_runtime.h>
#include <cuda_fp16.h>
#include <cstdint>
#include <cstddef>

// ---------------------------------------------------------------------------
// Problem dims
// ---------------------------------------------------------------------------
static constexpr int N_IN  = 2048;
static constexpr int N_HID = 4096;
static constexpr int N_OUT = 1024;
static constexpr int N_TOT = 7168;
static constexpr int BATCH = 4096;
static constexpr int KA    = N_IN + N_HID;   // 6144 : packed A = [x | hidden]

// ---------------------------------------------------------------------------
// Device scratch (allocation-free rule: __device__ globals)
// ---------------------------------------------------------------------------
__device__ __align__(1024) __half g_A[(size_t)BATCH * KA];       // [x | hidden] fp16
__device__ __align__(1024) __half g_B1[(size_t)N_HID * N_IN];    // W1^T fp16
__device__ __align__(1024) __half g_B2[(size_t)N_OUT * KA];      // W2^T fp16

#define DEVFN __device__ __forceinline__

DEVFN uint32_t smem_u32(const void* p) {
    uint32_t a;
    asm("{ .reg .u64 t; cvta.to.shared.u64 t, %1; cvt.u32.u64 %0, t; }"
        : "=r"(a) : "l"(p));
    return a;
}

DEVFN void cp16(uint32_t s, const void* g) {
    asm volatile("cp.async.cg.shared.global [%0], [%1], 16;"
                 :: "r"(s), "l"(g));
}
DEVFN void cp_commit() { asm volatile("cp.async.commit_group;"); }
template <int N> DEVFN void cp_wait() {
    asm volatile("cp.async.wait_group %0;" :: "n"(N));
}

DEVFN void ldsm4(uint32_t* r, uint32_t a) {
    asm volatile("ldmatrix.sync.aligned.m8n8.x4.shared.b16 {%0,%1,%2,%3}, [%4];"
                 : "=r"(r[0]), "=r"(r[1]), "=r"(r[2]), "=r"(r[3]) : "r"(a));
}

DEVFN void mma16816(float* d, const uint32_t* a, uint32_t b0, uint32_t b1) {
    asm volatile(
        "mma.sync.aligned.m16n8k16.row.col.f32.f16.f16.f32 "
        "{%0,%1,%2,%3}, {%4,%5,%6,%7}, {%8,%9}, {%0,%1,%2,%3};"
        : "+f"(d[0]), "+f"(d[1]), "+f"(d[2]), "+f"(d[3])
        : "r"(a[0]), "r"(a[1]), "r"(a[2]), "r"(a[3]), "r"(b0), "r"(b1));
}

DEVFN uint32_t pack2h(__half a, __half b) {
    return (uint32_t)__half_as_ushort(a) |
           ((uint32_t)__half_as_ushort(b) << 16);
}

// ---------------------------------------------------------------------------
// Packing kernels
// ---------------------------------------------------------------------------
__global__ void pack_x_kernel(const float4* __restrict__ x) {
    int idx = blockIdx.x * blockDim.x + threadIdx.x;   // over BATCH*N_IN/4
    int m  = idx / (N_IN / 4);
    int k4 = idx % (N_IN / 4);
    float4 v = x[idx];
    uint2 u;
    u.x = pack2h(__float2half(v.x), __float2half(v.y));
    u.y = pack2h(__float2half(v.z), __float2half(v.w));
    *(uint2*)(g_A + (size_t)m * KA + k4 * 4) = u;
}

// out[n][k] = fp16(W[k][col0 + n]) — tiled transpose
__global__ void pack_w_kernel(const float* __restrict__ W, int col0,
                              __half* __restrict__ outB, int pitchK) {
    __shared__ float t[32][33];
    int nb = blockIdx.x * 32, kb = blockIdx.y * 32;
    int tx = threadIdx.x, ty = threadIdx.y;   // (32, 8)
    #pragma unroll
    for (int i = 0; i < 4; i++) {
        int k = kb + ty + i * 8;
        t[ty + i * 8][tx] = W[(size_t)k * N_TOT + col0 + nb + tx];
    }
    __syncthreads();
    #pragma unroll
    for (int i = 0; i < 4; i++) {
        int n = nb + ty + i * 8;
        int k = kb + tx;
        outB[(size_t)n * pitchK + k] = __float2half(t[tx][ty + i * 8]);
    }
}

// ---------------------------------------------------------------------------
// fp16 GEMM on mma.sync (HMMA), cp.async 3-stage pipeline, fp32 accumulate.
// CTA tile 128(M) x 256(N); 8 warps, warp tile 64x64 (high smem reuse).
// K consumed in chunks of 64.
// ---------------------------------------------------------------------------
static constexpr int BM = 128, BN = 256, BK = 64;
static constexpr int STAGES  = 3;
static constexpr int A_TILE_B = BM * BK * 2;        // 16 KB
static constexpr int B_TILE_B = BN * BK * 2;        // 32 KB
static constexpr int STAGE_B  = A_TILE_B + B_TILE_B; // 48 KB
static constexpr int SMEM_GEMM = STAGES * STAGE_B + 128;   // ~144 KB

template <bool RELU_PACK>
__global__ __launch_bounds__(256, 1)
void gemm_f16(const __half* __restrict__ A, int ldA,
              const __half* __restrict__ B, int ldB,
              int kChunks,
              __half* __restrict__ outHalf, int outColOff,
              float* __restrict__ outF, int ldOut)
{
    extern __shared__ char smraw[];
    uint32_t sb = (smem_u32(smraw) + 127u) & ~127u;

    const int tid  = threadIdx.x;
    const int wid  = tid >> 5;
    const int lane = tid & 31;
    const int m0 = blockIdx.y * BM, n0 = blockIdx.x * BN;

    // ---- loader precompute (row*128B layout, XOR-swizzled 16B units) ----
    const int c16 = tid & 7;          // 16B unit within 128B row
    const int rb  = tid >> 3;         // base row (0..31)
    const uint32_t swz = (((uint32_t)c16 * 16) ^ (((uint32_t)rb & 7) << 4));
    const uint32_t srow0 = (uint32_t)rb * 128 + swz;

    const __half* gA = A + (size_t)(m0 + rb) * ldA + c16 * 8;
    const __half* gB = B + (size_t)(n0 + rb) * ldB + c16 * 8;

    auto load_stage = [&](int slot, int chunk) {
        uint32_t st = sb + slot * STAGE_B;
        int kcol = chunk * BK;
        #pragma unroll
        for (int j = 0; j < 4; j++)    // A: 128 rows
            cp16(st + srow0 + (uint32_t)(32 * j) * 128,
                 gA + (size_t)(32 * j) * ldA + kcol);
        #pragma unroll
        for (int j = 0; j < 8; j++)    // B: 256 rows
            cp16(st + A_TILE_B + srow0 + (uint32_t)(32 * j) * 128,
                 gB + (size_t)(32 * j) * ldB + kcol);
    };

    // ---- fragment address precompute (manual swizzle) ----
    const int warp_m = wid >> 2;      // 0..1 : 64 rows
    const int warp_n = wid & 3;       // 0..3 : 64 cols
    const uint32_t aOff0 = (uint32_t)(warp_m * 64 + (lane & 15)) * 128;
    const uint32_t aKq   = ((uint32_t)lane >> 4) * 16;
    const uint32_t amask = ((uint32_t)lane & 7) << 4;
    const uint32_t bOff0 =
        (uint32_t)(warp_n * 64 + (lane & 7) + ((lane >> 4) << 3)) * 128;
    const uint32_t bKq   = (((uint32_t)lane >> 3) & 1) * 16;
    const uint32_t bmask = ((uint32_t)lane & 7) << 4;

    float acc[4][8][4];
    #pragma unroll
    for (int mt = 0; mt < 4; mt++)
        #pragma unroll
        for (int nt = 0; nt < 8; nt++)
            #pragma unroll
            for (int r = 0; r < 4; r++)
                acc[mt][nt][r] = 0.0f;

    // ---- pipeline prologue: STAGES-1 groups in flight ----
    #pragma unroll
    for (int i = 0; i < STAGES - 1; i++) {
        if (i < kChunks) load_stage(i, i);
        cp_commit();
    }
    int issued = STAGES - 1;

    // ---- mainloop ----
    int s = 0;
    for (int c = 0; c < kChunks; c++) {
        cp_wait<STAGES - 2>();
        __syncthreads();

        int ns = s + (STAGES - 1); if (ns >= STAGES) ns -= STAGES;
        if (issued < kChunks) { load_stage(ns, issued); issued++; }
        cp_commit();

        uint32_t st = sb + s * STAGE_B;
        #pragma unroll
        for (int ks = 0; ks < 4; ks++) {          // each ks = 16 K-elements
            const uint32_t kb = ks * 32;          // byte offset along K
            uint32_t ah[4][4], bf[4][4];
            #pragma unroll
            for (int ng = 0; ng < 4; ng++)
                ldsm4(bf[ng], st + A_TILE_B + bOff0 + ng * 2048 + ((kb + bKq) ^ bmask));
            #pragma unroll
            for (int mt = 0; mt < 4; mt++)
                ldsm4(ah[mt], st + aOff0 + mt * 2048 + ((kb + aKq) ^ amask));

            #pragma unroll
            for (int mt = 0; mt < 4; mt++)
                #pragma unroll
                for (int nt = 0; nt < 8; nt++) {
                    const int ng = nt >> 1, hf = nt & 1;
                    mma16816(acc[mt][nt], ah[mt], bf[ng][hf * 2], bf[ng][hf * 2 + 1]);
                }
        }

        if (++s == STAGES) s = 0;
    }

    // ---- epilogue ----
    const int gr  = lane >> 2;        // 0..7
    const int gc2 = (lane & 3) * 2;   // 0,2,4,6
    #pragma unroll
    for (int mt = 0; mt < 4; mt++)
        #pragma unroll
        for (int nt = 0; nt < 8; nt++)
            #pragma unroll
            for (int hf = 0; hf < 2; hf++) {   // hf=0: c0,c1 ; hf=1: c2,c3
                int row = m0 + warp_m * 64 + mt * 16 + gr + hf * 8;
                int col = n0 + warp_n * 64 + nt * 8 + gc2;
                float v0 = acc[mt][nt][hf * 2];
                float v1 = acc[mt][nt][hf * 2 + 1];
                if (RELU_PACK) {
                    v0 = fmaxf(v0, 0.0f);
                    v1 = fmaxf(v1, 0.0f);
                    size_t o = (size_t)row * KA + outColOff + col;
                    *(uint32_t*)(outHalf + o) =
                        pack2h(__float2half(v0), __float2half(v1));
                } else {
                    *(float2*)(outF + (size_t)row * ldOut + col) =
                        make_float2(v0, v1);
                }
            }
}

// ---------------------------------------------------------------------------
// Host side
// ---------------------------------------------------------------------------
extern "C" void kernel_launch(void* const* d_in, const int* in_sizes, int n_in,
                              void* d_out, int out_size)
{
    const float* x = (const float*)d_in[0];        // (4096, 2048)
    const float* W = (const float*)d_in[1];        // (7168, 7168)
    float* out = (float*)d_out;                    // (4096, 1024)

    void *pA, *pB1, *pB2;
    cudaGetSymbolAddress(&pA,  g_A);
    cudaGetSymbolAddress(&pB1, g_B1);
    cudaGetSymbolAddress(&pB2, g_B2);

    cudaFuncSetAttribute(gemm_f16<true>,
        cudaFuncAttributeMaxDynamicSharedMemorySize, SMEM_GEMM);
    cudaFuncSetAttribute(gemm_f16<false>,
        cudaFuncAttributeMaxDynamicSharedMemorySize, SMEM_GEMM);

    // 1) pack x into A cols [0, 2048)
    pack_x_kernel<<<(BATCH * N_IN / 4) / 256, 256>>>((const float4*)x);

    // 2) transpose W slices to fp16 K-major
    pack_w_kernel<<<dim3(N_HID / 32, N_IN / 32), dim3(32, 8)>>>(
        W, N_IN, (__half*)pB1, N_IN);
    pack_w_kernel<<<dim3(N_OUT / 32, KA / 32), dim3(32, 8)>>>(
        W, N_IN + N_HID, (__half*)pB2, KA);

    // 3) GEMM1: hidden = relu(x @ W1); epilogue packs fp16 into A cols [2048,6144)
    gemm_f16<true><<<dim3(N_HID / BN, BATCH / BM), 256, SMEM_GEMM>>>(
        (const __half*)pA, KA,
        (const __half*)pB1, N_IN,
        N_IN / BK,
        (__half*)pA, N_IN, nullptr, 0);

    // 4) GEMM2: out = [x | hidden] @ W2
    gemm_f16<false><<<dim3(N_OUT / BN, BATCH / BM), 256, SMEM_GEMM>>>(
        (const __half*)pA, KA,
        (const __half*)pB2, KA,
        KA / BK,
        nullptr, 0, out, N_OUT);
}

// round 7
// speedup vs baseline: 1.0214x; 1.0214x over previous
#include <cuda_runtime.h>
#include <cuda_fp16.h>
#include <cstdint>
#include <cstddef>

// ---------------------------------------------------------------------------
// Problem dims
// ---------------------------------------------------------------------------
static constexpr int N_IN  = 2048;
static constexpr int N_HID = 4096;
static constexpr int N_OUT = 1024;
static constexpr int N_TOT = 7168;
static constexpr int BATCH = 4096;
static constexpr int KA    = N_IN + N_HID;   // 6144 : packed A = [x | hidden]

// ---------------------------------------------------------------------------
// Device scratch (allocation-free rule: __device__ globals)
// ---------------------------------------------------------------------------
__device__ __align__(1024) __half g_A[(size_t)BATCH * KA];       // [x | hidden] fp16
__device__ __align__(1024) __half g_B1[(size_t)N_HID * N_IN];    // W1^T fp16
__device__ __align__(1024) __half g_B2[(size_t)N_OUT * KA];      // W2^T fp16

#define DEVFN __device__ __forceinline__

DEVFN uint32_t smem_u32(const void* p) {
    uint32_t a;
    asm("{ .reg .u64 t; cvta.to.shared.u64 t, %1; cvt.u32.u64 %0, t; }"
        : "=r"(a) : "l"(p));
    return a;
}

DEVFN void cp16(uint32_t s, const void* g) {
    asm volatile("cp.async.cg.shared.global [%0], [%1], 16;"
                 :: "r"(s), "l"(g));
}
DEVFN void cp_commit() { asm volatile("cp.async.commit_group;"); }
template <int N> DEVFN void cp_wait() {
    asm volatile("cp.async.wait_group %0;" :: "n"(N));
}

DEVFN void ldsm4(uint32_t* r, uint32_t a) {
    asm volatile("ldmatrix.sync.aligned.m8n8.x4.shared.b16 {%0,%1,%2,%3}, [%4];"
                 : "=r"(r[0]), "=r"(r[1]), "=r"(r[2]), "=r"(r[3]) : "r"(a));
}

DEVFN void mma16816(float* d, const uint32_t* a, uint32_t b0, uint32_t b1) {
    asm volatile(
        "mma.sync.aligned.m16n8k16.row.col.f32.f16.f16.f32 "
        "{%0,%1,%2,%3}, {%4,%5,%6,%7}, {%8,%9}, {%0,%1,%2,%3};"
        : "+f"(d[0]), "+f"(d[1]), "+f"(d[2]), "+f"(d[3])
        : "r"(a[0]), "r"(a[1]), "r"(a[2]), "r"(a[3]), "r"(b0), "r"(b1));
}

DEVFN uint32_t pack2h(__half a, __half b) {
    return (uint32_t)__half_as_ushort(a) |
           ((uint32_t)__half_as_ushort(b) << 16);
}

// ---------------------------------------------------------------------------
// Packing kernels
// ---------------------------------------------------------------------------
__global__ void pack_x_kernel(const float4* __restrict__ x) {
    int idx = blockIdx.x * blockDim.x + threadIdx.x;   // over BATCH*N_IN/4
    int m  = idx / (N_IN / 4);
    int k4 = idx % (N_IN / 4);
    float4 v = x[idx];
    uint2 u;
    u.x = pack2h(__float2half(v.x), __float2half(v.y));
    u.y = pack2h(__float2half(v.z), __float2half(v.w));
    *(uint2*)(g_A + (size_t)m * KA + k4 * 4) = u;
}

// out[n][k] = fp16(W[k][col0 + n]) — tiled transpose, 128B-coalesced writes.
// Tile: k64 x n32. Block (32, 8).
__global__ void pack_w_kernel(const float* __restrict__ W, int col0,
                              __half* __restrict__ outB, int pitchK) {
    __shared__ float t[64][33];
    int nb = blockIdx.x * 32, kb = blockIdx.y * 64;
    int tx = threadIdx.x, ty = threadIdx.y;   // (32, 8)
    #pragma unroll
    for (int i = 0; i < 8; i++) {
        int k = kb + ty + i * 8;
        t[ty + i * 8][tx] = W[(size_t)k * N_TOT + col0 + nb + tx];
    }
    __syncthreads();
    #pragma unroll
    for (int i = 0; i < 4; i++) {
        int n = nb + ty + i * 8;
        int k2 = tx * 2;              // pair of k within tile
        uint32_t u = pack2h(__float2half(t[k2][ty + i * 8]),
                            __float2half(t[k2 + 1][ty + i * 8]));
        *(uint32_t*)(outB + (size_t)n * pitchK + kb + k2) = u;
    }
}

// ---------------------------------------------------------------------------
// fp16 GEMM on mma.sync (HMMA), cp.async 4-stage pipeline, fp32 accumulate.
// CTA tile 128(M) x 256(N); 8 warps (2x4), warp tile 64x64.
// Fragment double-buffering across k16 steps hides LDSM latency in-warp.
// ---------------------------------------------------------------------------
static constexpr int BM = 128, BN = 256, BK = 64;
static constexpr int STAGES  = 4;
static constexpr int A_TILE_B = BM * BK * 2;         // 16 KB
static constexpr int B_TILE_B = BN * BK * 2;         // 32 KB
static constexpr int STAGE_B  = A_TILE_B + B_TILE_B; // 48 KB
static constexpr int SMEM_GEMM = STAGES * STAGE_B + 128;   // ~192 KB

template <bool RELU_PACK>
__global__ __launch_bounds__(256, 1)
void gemm_f16(const __half* __restrict__ A, int ldA,
              const __half* __restrict__ B, int ldB,
              int kChunks,
              __half* __restrict__ outHalf, int outColOff,
              float* __restrict__ outF, int ldOut)
{
    extern __shared__ char smraw[];
    uint32_t sb = (smem_u32(smraw) + 127u) & ~127u;

    const int tid  = threadIdx.x;
    const int wid  = tid >> 5;
    const int lane = tid & 31;
    const int m0 = blockIdx.y * BM, n0 = blockIdx.x * BN;

    // ---- loader precompute (row*128B layout, XOR-swizzled 16B units) ----
    const int c16 = tid & 7;          // 16B unit within 128B row
    const int rb  = tid >> 3;         // base row (0..31)
    const uint32_t swz = (((uint32_t)c16 * 16) ^ (((uint32_t)rb & 7) << 4));
    const uint32_t srow0 = (uint32_t)rb * 128 + swz;

    const __half* gA = A + (size_t)(m0 + rb) * ldA + c16 * 8;
    const __half* gB = B + (size_t)(n0 + rb) * ldB + c16 * 8;

    auto load_stage = [&](int slot, int chunk) {
        uint32_t st = sb + slot * STAGE_B;
        int kcol = chunk * BK;
        #pragma unroll
        for (int j = 0; j < 4; j++)    // A: 128 rows
            cp16(st + srow0 + (uint32_t)(32 * j) * 128,
                 gA + (size_t)(32 * j) * ldA + kcol);
        #pragma unroll
        for (int j = 0; j < 8; j++)    // B: 256 rows
            cp16(st + A_TILE_B + srow0 + (uint32_t)(32 * j) * 128,
                 gB + (size_t)(32 * j) * ldB + kcol);
    };

    // ---- fragment address precompute (manual swizzle) ----
    const int warp_m = wid >> 2;      // 0..1 : 64 rows
    const int warp_n = wid & 3;       // 0..3 : 64 cols
    const uint32_t aOff0 = (uint32_t)(warp_m * 64 + (lane & 15)) * 128;
    const uint32_t aKq   = ((uint32_t)lane >> 4) * 16;
    const uint32_t amask = ((uint32_t)lane & 7) << 4;
    const uint32_t bOff0 =
        (uint32_t)(warp_n * 64 + (lane & 7) + ((lane >> 4) << 3)) * 128;
    const uint32_t bKq   = (((uint32_t)lane >> 3) & 1) * 16;
    const uint32_t bmask = ((uint32_t)lane & 7) << 4;

    // fragment loader for one k16 step (ks = 0..3 within chunk)
    auto ldfr = [&](uint32_t st, int ks, uint32_t (&ah)[4][4], uint32_t (&bf)[4][4]) {
        const uint32_t kb = (uint32_t)ks * 32;
        #pragma unroll
        for (int ng = 0; ng < 4; ng++)
            ldsm4(bf[ng], st + A_TILE_B + bOff0 + ng * 2048 + ((kb + bKq) ^ bmask));
        #pragma unroll
        for (int mt = 0; mt < 4; mt++)
            ldsm4(ah[mt], st + aOff0 + mt * 2048 + ((kb + aKq) ^ amask));
    };

    float acc[4][8][4];
    #pragma unroll
    for (int mt = 0; mt < 4; mt++)
        #pragma unroll
        for (int nt = 0; nt < 8; nt++)
            #pragma unroll
            for (int r = 0; r < 4; r++)
                acc[mt][nt][r] = 0.0f;

    // ---- pipeline prologue: STAGES-1 groups in flight ----
    #pragma unroll
    for (int i = 0; i < STAGES - 1; i++) {
        if (i < kChunks) load_stage(i, i);
        cp_commit();
    }
    int issued = STAGES - 1;

    uint32_t ah[2][4][4], bf[2][4][4];

    // ---- mainloop ----
    int s = 0;
    for (int c = 0; c < kChunks; c++) {
        cp_wait<STAGES - 2>();     // chunk c's data resident
        __syncthreads();

        int ns = s + (STAGES - 1); if (ns >= STAGES) ns -= STAGES;
        if (issued < kChunks) { load_stage(ns, issued); issued++; }
        cp_commit();

        uint32_t st = sb + s * STAGE_B;
        ldfr(st, 0, ah[0], bf[0]);

        #pragma unroll
        for (int ks = 0; ks < 4; ks++) {
            const int cur = ks & 1;
            if (ks < 3) ldfr(st, ks + 1, ah[cur ^ 1], bf[cur ^ 1]);

            #pragma unroll
            for (int mt = 0; mt < 4; mt++)
                #pragma unroll
                for (int nt = 0; nt < 8; nt++) {
                    const int ng = nt >> 1, hf = nt & 1;
                    mma16816(acc[mt][nt], ah[cur][mt],
                             bf[cur][ng][hf * 2], bf[cur][ng][hf * 2 + 1]);
                }
        }

        if (++s == STAGES) s = 0;
    }

    // ---- epilogue ----
    const int gr  = lane >> 2;        // 0..7
    const int gc2 = (lane & 3) * 2;   // 0,2,4,6
    #pragma unroll
    for (int mt = 0; mt < 4; mt++)
        #pragma unroll
        for (int nt = 0; nt < 8; nt++)
            #pragma unroll
            for (int hf = 0; hf < 2; hf++) {   // hf=0: c0,c1 ; hf=1: c2,c3
                int row = m0 + warp_m * 64 + mt * 16 + gr + hf * 8;
                int col = n0 + warp_n * 64 + nt * 8 + gc2;
                float v0 = acc[mt][nt][hf * 2];
                float v1 = acc[mt][nt][hf * 2 + 1];
                if (RELU_PACK) {
                    v0 = fmaxf(v0, 0.0f);
                    v1 = fmaxf(v1, 0.0f);
                    size_t o = (size_t)row * KA + outColOff + col;
                    *(uint32_t*)(outHalf + o) =
                        pack2h(__float2half(v0), __float2half(v1));
                } else {
                    *(float2*)(outF + (size_t)row * ldOut + col) =
                        make_float2(v0, v1);
                }
            }
}

// ---------------------------------------------------------------------------
// Host side
// ---------------------------------------------------------------------------
extern "C" void kernel_launch(void* const* d_in, const int* in_sizes, int n_in,
                              void* d_out, int out_size)
{
    const float* x = (const float*)d_in[0];        // (4096, 2048)
    const float* W = (const float*)d_in[1];        // (7168, 7168)
    float* out = (float*)d_out;                    // (4096, 1024)

    void *pA, *pB1, *pB2;
    cudaGetSymbolAddress(&pA,  g_A);
    cudaGetSymbolAddress(&pB1, g_B1);
    cudaGetSymbolAddress(&pB2, g_B2);

    cudaFuncSetAttribute(gemm_f16<true>,
        cudaFuncAttributeMaxDynamicSharedMemorySize, SMEM_GEMM);
    cudaFuncSetAttribute(gemm_f16<false>,
        cudaFuncAttributeMaxDynamicSharedMemorySize, SMEM_GEMM);

    // 1) pack x into A cols [0, 2048)
    pack_x_kernel<<<(BATCH * N_IN / 4) / 256, 256>>>((const float4*)x);

    // 2) transpose W slices to fp16 K-major
    pack_w_kernel<<<dim3(N_HID / 32, N_IN / 64), dim3(32, 8)>>>(
        W, N_IN, (__half*)pB1, N_IN);
    pack_w_kernel<<<dim3(N_OUT / 32, KA / 64), dim3(32, 8)>>>(
        W, N_IN + N_HID, (__half*)pB2, KA);

    // 3) GEMM1: hidden = relu(x @ W1); epilogue packs fp16 into A cols [2048,6144)
    gemm_f16<true><<<dim3(N_HID / BN, BATCH / BM), 256, SMEM_GEMM>>>(
        (const __half*)pA, KA,
        (const __half*)pB1, N_IN,
        N_IN / BK,
        (__half*)pA, N_IN, nullptr, 0);

    // 4) GEMM2: out = [x | hidden] @ W2
    gemm_f16<false><<<dim3(N_OUT / BN, BATCH / BM), 256, SMEM_GEMM>>>(
        (const __half*)pA, KA,
        (const __half*)pB2, KA,
        KA / BK,
        nullptr, 0, out, N_OUT);
}

// round 8
// speedup vs baseline: 1.1246x; 1.1010x over previous
#include <cuda_runtime.h>
#include <cuda_fp16.h>
#include <cstdint>
#include <cstddef>

// ---------------------------------------------------------------------------
// Problem dims
// ---------------------------------------------------------------------------
static constexpr int N_IN  = 2048;
static constexpr int N_HID = 4096;
static constexpr int N_OUT = 1024;
static constexpr int N_TOT = 7168;
static constexpr int BATCH = 4096;
static constexpr int KA    = N_IN + N_HID;   // 6144 : packed A = [x | hidden]

// ---------------------------------------------------------------------------
// Device scratch (allocation-free rule: __device__ globals)
// ---------------------------------------------------------------------------
__device__ __align__(1024) __half g_A[(size_t)BATCH * KA];       // [x | hidden] fp16
__device__ __align__(1024) __half g_B1[(size_t)N_HID * N_IN];    // W1^T fp16
__device__ __align__(1024) __half g_B2[(size_t)N_OUT * KA];      // W2^T fp16

#define DEVFN __device__ __forceinline__

DEVFN uint32_t smem_u32(const void* p) {
    uint32_t a;
    asm("{ .reg .u64 t; cvta.to.shared.u64 t, %1; cvt.u32.u64 %0, t; }"
        : "=r"(a) : "l"(p));
    return a;
}

DEVFN void cp16(uint32_t s, const void* g) {
    asm volatile("cp.async.cg.shared.global [%0], [%1], 16;"
                 :: "r"(s), "l"(g));
}
DEVFN void cp_commit() { asm volatile("cp.async.commit_group;"); }
template <int N> DEVFN void cp_wait() {
    asm volatile("cp.async.wait_group %0;" :: "n"(N));
}

DEVFN void ldsm4(uint32_t* r, uint32_t a) {
    asm volatile("ldmatrix.sync.aligned.m8n8.x4.shared.b16 {%0,%1,%2,%3}, [%4];"
                 : "=r"(r[0]), "=r"(r[1]), "=r"(r[2]), "=r"(r[3]) : "r"(a));
}

DEVFN void mma16816(float* d, const uint32_t* a, uint32_t b0, uint32_t b1) {
    asm volatile(
        "mma.sync.aligned.m16n8k16.row.col.f32.f16.f16.f32 "
        "{%0,%1,%2,%3}, {%4,%5,%6,%7}, {%8,%9}, {%0,%1,%2,%3};"
        : "+f"(d[0]), "+f"(d[1]), "+f"(d[2]), "+f"(d[3])
        : "r"(a[0]), "r"(a[1]), "r"(a[2]), "r"(a[3]), "r"(b0), "r"(b1));
}

DEVFN uint32_t pack2h(__half a, __half b) {
    return (uint32_t)__half_as_ushort(a) |
           ((uint32_t)__half_as_ushort(b) << 16);
}

// ---------------------------------------------------------------------------
// Packing kernels
// ---------------------------------------------------------------------------
__global__ void pack_x_kernel(const float4* __restrict__ x) {
    int idx = blockIdx.x * blockDim.x + threadIdx.x;   // over BATCH*N_IN/4
    int m  = idx / (N_IN / 4);
    int k4 = idx % (N_IN / 4);
    float4 v = x[idx];
    uint2 u;
    u.x = pack2h(__float2half(v.x), __float2half(v.y));
    u.y = pack2h(__float2half(v.z), __float2half(v.w));
    *(uint2*)(g_A + (size_t)m * KA + k4 * 4) = u;
}

// out[n][k] = fp16(W[k][col0 + n]) — tiled transpose, coalesced 128B writes.
// Tile: k64 x n32. Block (32, 8).
__global__ void pack_w_kernel(const float* __restrict__ W, int col0,
                              __half* __restrict__ outB, int pitchK) {
    __shared__ float t[64][33];
    int nb = blockIdx.x * 32, kb = blockIdx.y * 64;
    int tx = threadIdx.x, ty = threadIdx.y;   // (32, 8)
    #pragma unroll
    for (int i = 0; i < 8; i++) {
        int k = kb + ty + i * 8;
        t[ty + i * 8][tx] = W[(size_t)k * N_TOT + col0 + nb + tx];
    }
    __syncthreads();
    #pragma unroll
    for (int i = 0; i < 4; i++) {
        int n = nb + ty + i * 8;
        int k2 = tx * 2;              // pair of k within tile
        uint32_t u = pack2h(__float2half(t[k2][ty + i * 8]),
                            __float2half(t[k2 + 1][ty + i * 8]));
        *(uint32_t*)(outB + (size_t)n * pitchK + kb + k2) = u;
    }
}

// ---------------------------------------------------------------------------
// fp16 GEMM on mma.sync, cp.async 3-stage pipeline, fp32 accumulate.
// CTA tile 128x128, 8 warps (2x4), warp tile 64x32, 2 CTAs/SM.  (R4 config)
//
// phase 0 grid = 1024 + 256 blocks:
//   bid <  1024 : GEMM1 tile   hidden = relu(x @ W1)  -> pack fp16 into g_A
//   bid >= 1024 : GEMM2a tile  out    = x @ W2[0:2048]          (f32 store)
// GEMM2a depends only on x, so its tiles fill GEMM1's wave-quantization tail.
// phase 1 grid = 256 blocks:
//   GEMM2b tile  out += hidden @ W2[2048:6144]        (f32 accumulate)
// ---------------------------------------------------------------------------
static constexpr int BM = 128, BN = 128, BK = 64;
static constexpr int STAGES  = 3;
static constexpr int TILE_B  = BM * BK * 2;        // 16 KB
static constexpr int STAGE_B = 2 * TILE_B;         // A + B = 32 KB
static constexpr int SMEM_GEMM = STAGES * STAGE_B + 128;   // ~96 KB

static constexpr int G1_TILES  = (BATCH / BM) * (N_HID / BN);  // 1024
static constexpr int G2_TILESX = N_OUT / BN;                    // 8

__global__ __launch_bounds__(256, 2)
void net_gemm(float* __restrict__ out, int phase)
{
    extern __shared__ char smraw[];
    uint32_t sb = (smem_u32(smraw) + 127u) & ~127u;

    const int tid  = threadIdx.x;
    const int wid  = tid >> 5;
    const int lane = tid & 31;
    const int bid  = blockIdx.x;

    // ---- mode resolve ----
    const __half *Abase, *Bbase;
    int ldA, ldB, kc, epi, m0, n0;
    if (phase == 0) {
        if (bid < G1_TILES) {               // GEMM1
            m0 = (bid >> 5) * BM; n0 = (bid & 31) * BN;
            Abase = g_A;  ldA = KA;
            Bbase = g_B1; ldB = N_IN;
            kc = N_IN / BK;  epi = 0;
        } else {                            // GEMM2a : x @ W2[0:2048]
            int t = bid - G1_TILES;
            m0 = (t >> 3) * BM; n0 = (t & 7) * BN;
            Abase = g_A;  ldA = KA;
            Bbase = g_B2; ldB = KA;
            kc = N_IN / BK;  epi = 1;
        }
    } else {                                // GEMM2b : hidden @ W2[2048:]
        m0 = (bid >> 3) * BM; n0 = (bid & 7) * BN;
        Abase = g_A + N_IN;  ldA = KA;
        Bbase = g_B2 + N_IN; ldB = KA;
        kc = (KA - N_IN) / BK;  epi = 2;
    }

    // ---- loader precompute: each thread moves 4x16B per tile per stage ----
    const int c16 = tid & 7;          // 16B unit within 128B row
    const int rb  = tid >> 3;         // base row (0..31)
    const uint32_t lxor = (uint32_t)(rb & 7) << 4;
    uint32_t soff[4];
    #pragma unroll
    for (int j = 0; j < 4; j++)
        soff[j] = (uint32_t)(rb + 32 * j) * 128 + (((uint32_t)c16 * 16) ^ lxor);

    const __half* gA = Abase + (size_t)(m0 + rb) * ldA + c16 * 8;
    const __half* gB = Bbase + (size_t)(n0 + rb) * ldB + c16 * 8;

    auto load_stage = [&](int slot, int chunk) {
        uint32_t st = sb + slot * STAGE_B;
        int kcol = chunk * BK;
        #pragma unroll
        for (int j = 0; j < 4; j++) {
            cp16(st + soff[j],          gA + (size_t)(32 * j) * ldA + kcol);
            cp16(st + TILE_B + soff[j], gB + (size_t)(32 * j) * ldB + kcol);
        }
    };

    // ---- fragment address precompute (manual SW128 swizzle) ----
    const int warp_m = wid >> 2;      // 0..1, 64 rows each
    const int warp_n = wid & 3;       // 0..3, 32 cols each
    const uint32_t aOff0 = (uint32_t)(warp_m * 64 + (lane & 15)) * 128;
    const uint32_t aKq   = ((uint32_t)lane >> 4) * 16;
    const uint32_t amask = ((uint32_t)lane & 7) << 4;
    const uint32_t bOff0 =
        (uint32_t)(warp_n * 32 + (lane & 7) + ((lane >> 4) << 3)) * 128;
    const uint32_t bKq   = (((uint32_t)lane >> 3) & 1) * 16;
    const uint32_t bmask = ((uint32_t)lane & 7) << 4;

    float acc[4][4][4];
    #pragma unroll
    for (int mt = 0; mt < 4; mt++)
        #pragma unroll
        for (int nt = 0; nt < 4; nt++)
            #pragma unroll
            for (int r = 0; r < 4; r++)
                acc[mt][nt][r] = 0.0f;

    // ---- pipeline prologue ----
    int pro = kc < STAGES ? kc : STAGES;
    for (int i = 0; i < pro; i++) { load_stage(i, i); cp_commit(); }
    int issued = pro;

    // ---- mainloop (R4 structure) ----
    int s = 0;
    for (int c = 0; c < kc; c++) {
        cp_wait<STAGES - 1>();
        __syncthreads();
        uint32_t st = sb + s * STAGE_B;

        #pragma unroll
        for (int ks = 0; ks < 4; ks++) {
            const uint32_t kb = ks * 32;
            uint32_t ah[4][4], bf[2][4];
            #pragma unroll
            for (int mt = 0; mt < 4; mt++)
                ldsm4(ah[mt], st + aOff0 + mt * 2048 + ((kb + aKq) ^ amask));
            #pragma unroll
            for (int ng = 0; ng < 2; ng++)
                ldsm4(bf[ng], st + TILE_B + bOff0 + ng * 2048 + ((kb + bKq) ^ bmask));

            #pragma unroll
            for (int mt = 0; mt < 4; mt++)
                #pragma unroll
                for (int nt = 0; nt < 4; nt++) {
                    const int ng = nt >> 1, hf = nt & 1;
                    mma16816(acc[mt][nt], ah[mt], bf[ng][hf * 2], bf[ng][hf * 2 + 1]);
                }
        }

        __syncthreads();
        if (issued < kc) { load_stage(s, issued); issued++; }
        cp_commit();
        if (++s == STAGES) s = 0;
    }

    // ---- epilogue ----
    const int gr  = lane >> 2;        // 0..7
    const int gc2 = (lane & 3) * 2;   // 0,2,4,6
    #pragma unroll
    for (int mt = 0; mt < 4; mt++)
        #pragma unroll
        for (int nt = 0; nt < 4; nt++)
            #pragma unroll
            for (int hf = 0; hf < 2; hf++) {   // hf=0: c0,c1 ; hf=1: c2,c3
                int row = m0 + warp_m * 64 + mt * 16 + gr + hf * 8;
                int col = n0 + warp_n * 32 + nt * 8 + gc2;
                float v0 = acc[mt][nt][hf * 2];
                float v1 = acc[mt][nt][hf * 2 + 1];
                if (epi == 0) {
                    v0 = fmaxf(v0, 0.0f);
                    v1 = fmaxf(v1, 0.0f);
                    size_t o = (size_t)row * KA + N_IN + col;
                    *(uint32_t*)(g_A + o) =
                        pack2h(__float2half(v0), __float2half(v1));
                } else {
                    float2* op = (float2*)(out + (size_t)row * N_OUT + col);
                    if (epi == 2) {
                        float2 prev = *op;
                        v0 += prev.x; v1 += prev.y;
                    }
                    *op = make_float2(v0, v1);
                }
            }
}

// ---------------------------------------------------------------------------
// Host side
// ---------------------------------------------------------------------------
extern "C" void kernel_launch(void* const* d_in, const int* in_sizes, int n_in,
                              void* d_out, int out_size)
{
    const float* x = (const float*)d_in[0];        // (4096, 2048)
    const float* W = (const float*)d_in[1];        // (7168, 7168)
    float* out = (float*)d_out;                    // (4096, 1024)

    void *pB1, *pB2;
    cudaGetSymbolAddress(&pB1, g_B1);
    cudaGetSymbolAddress(&pB2, g_B2);

    cudaFuncSetAttribute(net_gemm,
        cudaFuncAttributeMaxDynamicSharedMemorySize, SMEM_GEMM);

    // 1) pack x into A cols [0, 2048)
    pack_x_kernel<<<(BATCH * N_IN / 4) / 256, 256>>>((const float4*)x);

    // 2) transpose W slices to fp16 K-major
    pack_w_kernel<<<dim3(N_HID / 32, N_IN / 64), dim3(32, 8)>>>(
        W, N_IN, (__half*)pB1, N_IN);
    pack_w_kernel<<<dim3(N_OUT / 32, KA / 64), dim3(32, 8)>>>(
        W, N_IN + N_HID, (__half*)pB2, KA);

    // 3) phase 0: GEMM1 (1024 tiles) + GEMM2a (256 tiles, x-only K range)
    net_gemm<<<G1_TILES + (BATCH / BM) * G2_TILESX, 256, SMEM_GEMM>>>(out, 0);

    // 4) phase 1: GEMM2b accumulate (hidden K range)
    net_gemm<<<(BATCH / BM) * G2_TILESX, 256, SMEM_GEMM>>>(out, 1);
}

// round 9
// speedup vs baseline: 1.1736x; 1.0436x over previous
#include <cuda_runtime.h>
#include <cuda_fp16.h>
#include <cstdint>
#include <cstddef>

// ---------------------------------------------------------------------------
// Problem dims
// ---------------------------------------------------------------------------
static constexpr int N_IN  = 2048;
static constexpr int N_HID = 4096;
static constexpr int N_OUT = 1024;
static constexpr int N_TOT = 7168;
static constexpr int BATCH = 4096;
static constexpr int KA    = N_IN + N_HID;   // 6144 : packed A = [x | hidden]

// ---------------------------------------------------------------------------
// Device scratch (allocation-free rule: __device__ globals)
// ---------------------------------------------------------------------------
__device__ __align__(1024) __half g_A[(size_t)BATCH * KA];       // [x | hidden] fp16
__device__ __align__(1024) __half g_B1[(size_t)N_HID * N_IN];    // W1^T fp16
__device__ __align__(1024) __half g_B2[(size_t)N_OUT * KA];      // W2^T fp16

#define DEVFN __device__ __forceinline__

DEVFN uint32_t smem_u32(const void* p) {
    uint32_t a;
    asm("{ .reg .u64 t; cvta.to.shared.u64 t, %1; cvt.u32.u64 %0, t; }"
        : "=r"(a) : "l"(p));
    return a;
}

DEVFN void cp16(uint32_t s, const void* g) {
    asm volatile("cp.async.cg.shared.global [%0], [%1], 16;"
                 :: "r"(s), "l"(g));
}
DEVFN void cp_commit() { asm volatile("cp.async.commit_group;"); }
template <int N> DEVFN void cp_wait() {
    asm volatile("cp.async.wait_group %0;" :: "n"(N));
}

DEVFN void ldsm4(uint32_t* r, uint32_t a) {
    asm volatile("ldmatrix.sync.aligned.m8n8.x4.shared.b16 {%0,%1,%2,%3}, [%4];"
                 : "=r"(r[0]), "=r"(r[1]), "=r"(r[2]), "=r"(r[3]) : "r"(a));
}

DEVFN void mma16816(float* d, const uint32_t* a, uint32_t b0, uint32_t b1) {
    asm volatile(
        "mma.sync.aligned.m16n8k16.row.col.f32.f16.f16.f32 "
        "{%0,%1,%2,%3}, {%4,%5,%6,%7}, {%8,%9}, {%0,%1,%2,%3};"
        : "+f"(d[0]), "+f"(d[1]), "+f"(d[2]), "+f"(d[3])
        : "r"(a[0]), "r"(a[1]), "r"(a[2]), "r"(a[3]), "r"(b0), "r"(b1));
}

DEVFN uint32_t pack2h(__half a, __half b) {
    return (uint32_t)__half_as_ushort(a) |
           ((uint32_t)__half_as_ushort(b) << 16);
}

// ---------------------------------------------------------------------------
// Packing kernels
// ---------------------------------------------------------------------------
__global__ void pack_x_kernel(const float4* __restrict__ x) {
    int idx = blockIdx.x * blockDim.x + threadIdx.x;   // over BATCH*N_IN/4
    int m  = idx / (N_IN / 4);
    int k4 = idx % (N_IN / 4);
    float4 v = x[idx];
    uint2 u;
    u.x = pack2h(__float2half(v.x), __float2half(v.y));
    u.y = pack2h(__float2half(v.z), __float2half(v.w));
    *(uint2*)(g_A + (size_t)m * KA + k4 * 4) = u;
}

// out[n][k] = fp16(W[k][col0 + n]) — tiled transpose, coalesced 128B writes.
// Tile: k64 x n32. Block (32, 8).
__global__ void pack_w_kernel(const float* __restrict__ W, int col0,
                              __half* __restrict__ outB, int pitchK) {
    __shared__ float t[64][33];
    int nb = blockIdx.x * 32, kb = blockIdx.y * 64;
    int tx = threadIdx.x, ty = threadIdx.y;   // (32, 8)
    #pragma unroll
    for (int i = 0; i < 8; i++) {
        int k = kb + ty + i * 8;
        t[ty + i * 8][tx] = W[(size_t)k * N_TOT + col0 + nb + tx];
    }
    __syncthreads();
    #pragma unroll
    for (int i = 0; i < 4; i++) {
        int n = nb + ty + i * 8;
        int k2 = tx * 2;              // pair of k within tile
        uint32_t u = pack2h(__float2half(t[k2][ty + i * 8]),
                            __float2half(t[k2 + 1][ty + i * 8]));
        *(uint32_t*)(outB + (size_t)n * pitchK + kb + k2) = u;
    }
}

// ---------------------------------------------------------------------------
// fp16 GEMM on mma.sync, cp.async 3-stage pipeline, fp32 accumulate.
// CTA tile 128x128 with ONLY 128 threads: 4 warps (2x2), warp tile 64x64.
// 2 CTAs/SM -> barrier bubbles of one CTA covered by the other, while the
// 64x64 warp tile keeps smem crossbar demand at ~0.68x tensor demand.
//
// phase 0 grid = 1024 + 256 blocks:
//   bid <  1024 : GEMM1 tile   hidden = relu(x @ W1)  -> pack fp16 into g_A
//   bid >= 1024 : GEMM2a tile  out    = x @ W2[0:2048]          (f32 store)
// phase 1 grid = 256 blocks:
//   GEMM2b tile  out += hidden @ W2[2048:6144]        (f32 accumulate)
// ---------------------------------------------------------------------------
static constexpr int BM = 128, BN = 128, BK = 64;
static constexpr int STAGES  = 3;
static constexpr int TILE_B  = BM * BK * 2;        // 16 KB
static constexpr int STAGE_B = 2 * TILE_B;         // A + B = 32 KB
static constexpr int SMEM_GEMM = STAGES * STAGE_B + 128;   // ~96 KB

static constexpr int G1_TILES  = (BATCH / BM) * (N_HID / BN);  // 1024
static constexpr int G2_TILESX = N_OUT / BN;                    // 8

__global__ __launch_bounds__(128, 2)
void net_gemm(float* __restrict__ out, int phase)
{
    extern __shared__ char smraw[];
    uint32_t sb = (smem_u32(smraw) + 127u) & ~127u;

    const int tid  = threadIdx.x;
    const int wid  = tid >> 5;
    const int lane = tid & 31;
    const int bid  = blockIdx.x;

    // ---- mode resolve ----
    const __half *Abase, *Bbase;
    int ldA, ldB, kc, epi, m0, n0;
    if (phase == 0) {
        if (bid < G1_TILES) {               // GEMM1
            m0 = (bid >> 5) * BM; n0 = (bid & 31) * BN;
            Abase = g_A;  ldA = KA;
            Bbase = g_B1; ldB = N_IN;
            kc = N_IN / BK;  epi = 0;
        } else {                            // GEMM2a : x @ W2[0:2048]
            int t = bid - G1_TILES;
            m0 = (t >> 3) * BM; n0 = (t & 7) * BN;
            Abase = g_A;  ldA = KA;
            Bbase = g_B2; ldB = KA;
            kc = N_IN / BK;  epi = 1;
        }
    } else {                                // GEMM2b : hidden @ W2[2048:]
        m0 = (bid >> 3) * BM; n0 = (bid & 7) * BN;
        Abase = g_A + N_IN;  ldA = KA;
        Bbase = g_B2 + N_IN; ldB = KA;
        kc = (KA - N_IN) / BK;  epi = 2;
    }

    // ---- loader precompute: 128 threads, 16 rows per pass, 8 passes/tile ----
    const int c16 = tid & 7;          // 16B unit within 128B row
    const int rb  = tid >> 3;         // base row (0..15)
    const uint32_t lxor = (uint32_t)(rb & 7) << 4;
    const uint32_t srow0 = (uint32_t)rb * 128 + (((uint32_t)c16 * 16) ^ lxor);

    const __half* gA = Abase + (size_t)(m0 + rb) * ldA + c16 * 8;
    const __half* gB = Bbase + (size_t)(n0 + rb) * ldB + c16 * 8;

    auto load_stage = [&](int slot, int chunk) {
        uint32_t st = sb + slot * STAGE_B;
        int kcol = chunk * BK;
        #pragma unroll
        for (int j = 0; j < 8; j++) {
            cp16(st + srow0 + (uint32_t)(16 * j) * 128,
                 gA + (size_t)(16 * j) * ldA + kcol);
            cp16(st + TILE_B + srow0 + (uint32_t)(16 * j) * 128,
                 gB + (size_t)(16 * j) * ldB + kcol);
        }
    };

    // ---- fragment address precompute (manual swizzle) ----
    const int warp_m = wid >> 1;      // 0..1 : 64 rows
    const int warp_n = wid & 1;       // 0..1 : 64 cols
    const uint32_t aOff0 = (uint32_t)(warp_m * 64 + (lane & 15)) * 128;
    const uint32_t aKq   = ((uint32_t)lane >> 4) * 16;
    const uint32_t amask = ((uint32_t)lane & 7) << 4;
    const uint32_t bOff0 =
        (uint32_t)(warp_n * 64 + (lane & 7) + ((lane >> 4) << 3)) * 128;
    const uint32_t bKq   = (((uint32_t)lane >> 3) & 1) * 16;
    const uint32_t bmask = ((uint32_t)lane & 7) << 4;

    float acc[4][8][4];
    #pragma unroll
    for (int mt = 0; mt < 4; mt++)
        #pragma unroll
        for (int nt = 0; nt < 8; nt++)
            #pragma unroll
            for (int r = 0; r < 4; r++)
                acc[mt][nt][r] = 0.0f;

    // ---- pipeline prologue ----
    int pro = kc < STAGES ? kc : STAGES;
    for (int i = 0; i < pro; i++) { load_stage(i, i); cp_commit(); }
    int issued = pro;

    // ---- mainloop ----
    int s = 0;
    for (int c = 0; c < kc; c++) {
        cp_wait<STAGES - 1>();
        __syncthreads();
        uint32_t st = sb + s * STAGE_B;

        #pragma unroll
        for (int ks = 0; ks < 4; ks++) {
            const uint32_t kb = ks * 32;
            uint32_t ah[4][4], bf[4][4];
            #pragma unroll
            for (int ng = 0; ng < 4; ng++)
                ldsm4(bf[ng], st + TILE_B + bOff0 + ng * 2048 + ((kb + bKq) ^ bmask));
            #pragma unroll
            for (int mt = 0; mt < 4; mt++)
                ldsm4(ah[mt], st + aOff0 + mt * 2048 + ((kb + aKq) ^ amask));

            #pragma unroll
            for (int mt = 0; mt < 4; mt++)
                #pragma unroll
                for (int nt = 0; nt < 8; nt++) {
                    const int ng = nt >> 1, hf = nt & 1;
                    mma16816(acc[mt][nt], ah[mt], bf[ng][hf * 2], bf[ng][hf * 2 + 1]);
                }
        }

        __syncthreads();
        if (issued < kc) { load_stage(s, issued); issued++; }
        cp_commit();
        if (++s == STAGES) s = 0;
    }

    // ---- epilogue ----
    const int gr  = lane >> 2;        // 0..7
    const int gc2 = (lane & 3) * 2;   // 0,2,4,6
    #pragma unroll
    for (int mt = 0; mt < 4; mt++)
        #pragma unroll
        for (int nt = 0; nt < 8; nt++)
            #pragma unroll
            for (int hf = 0; hf < 2; hf++) {   // hf=0: c0,c1 ; hf=1: c2,c3
                int row = m0 + warp_m * 64 + mt * 16 + gr + hf * 8;
                int col = n0 + warp_n * 64 + nt * 8 + gc2;
                float v0 = acc[mt][nt][hf * 2];
                float v1 = acc[mt][nt][hf * 2 + 1];
                if (epi == 0) {
                    v0 = fmaxf(v0, 0.0f);
                    v1 = fmaxf(v1, 0.0f);
                    size_t o = (size_t)row * KA + N_IN + col;
                    *(uint32_t*)(g_A + o) =
                        pack2h(__float2half(v0), __float2half(v1));
                } else {
                    float2* op = (float2*)(out + (size_t)row * N_OUT + col);
                    if (epi == 2) {
                        float2 prev = *op;
                        v0 += prev.x; v1 += prev.y;
                    }
                    *op = make_float2(v0, v1);
                }
            }
}

// ---------------------------------------------------------------------------
// Host side
// ---------------------------------------------------------------------------
extern "C" void kernel_launch(void* const* d_in, const int* in_sizes, int n_in,
                              void* d_out, int out_size)
{
    const float* x = (const float*)d_in[0];        // (4096, 2048)
    const float* W = (const float*)d_in[1];        // (7168, 7168)
    float* out = (float*)d_out;                    // (4096, 1024)

    void *pB1, *pB2;
    cudaGetSymbolAddress(&pB1, g_B1);
    cudaGetSymbolAddress(&pB2, g_B2);

    cudaFuncSetAttribute(net_gemm,
        cudaFuncAttributeMaxDynamicSharedMemorySize, SMEM_GEMM);

    // 1) pack x into A cols [0, 2048)
    pack_x_kernel<<<(BATCH * N_IN / 4) / 256, 256>>>((const float4*)x);

    // 2) transpose W slices to fp16 K-major
    pack_w_kernel<<<dim3(N_HID / 32, N_IN / 64), dim3(32, 8)>>>(
        W, N_IN, (__half*)pB1, N_IN);
    pack_w_kernel<<<dim3(N_OUT / 32, KA / 64), dim3(32, 8)>>>(
        W, N_IN + N_HID, (__half*)pB2, KA);

    // 3) phase 0: GEMM1 (1024 tiles) + GEMM2a (256 tiles, x-only K range)
    net_gemm<<<G1_TILES + (BATCH / BM) * G2_TILESX, 128, SMEM_GEMM>>>(out, 0);

    // 4) phase 1: GEMM2b accumulate (hidden K range)
    net_gemm<<<(BATCH / BM) * G2_TILESX, 128, SMEM_GEMM>>>(out, 1);
}

// round 10
// speedup vs baseline: 1.2113x; 1.0321x over previous
#include <cuda_runtime.h>
#include <cuda_fp16.h>
#include <cstdint>
#include <cstddef>

// ---------------------------------------------------------------------------
// Problem dims
// ---------------------------------------------------------------------------
static constexpr int N_IN  = 2048;
static constexpr int N_HID = 4096;
static constexpr int N_OUT = 1024;
static constexpr int N_TOT = 7168;
static constexpr int BATCH = 4096;
static constexpr int KA    = N_IN + N_HID;   // 6144 : packed A = [x | hidden]

// ---------------------------------------------------------------------------
// Device scratch (allocation-free rule: __device__ globals)
// ---------------------------------------------------------------------------
__device__ __align__(1024) __half g_A[(size_t)BATCH * KA];       // [x | hidden] fp16
__device__ __align__(1024) __half g_B1[(size_t)N_HID * N_IN];    // W1^T fp16
__device__ __align__(1024) __half g_B2[(size_t)N_OUT * KA];      // W2^T fp16
__device__ int g_cnt[BATCH / 128];   // per 128-row block: # finished GEMM1 tiles

#define DEVFN __device__ __forceinline__

DEVFN uint32_t smem_u32(const void* p) {
    uint32_t a;
    asm("{ .reg .u64 t; cvta.to.shared.u64 t, %1; cvt.u32.u64 %0, t; }"
        : "=r"(a) : "l"(p));
    return a;
}

DEVFN void cp16(uint32_t s, const void* g) {
    asm volatile("cp.async.cg.shared.global [%0], [%1], 16;"
                 :: "r"(s), "l"(g));
}
DEVFN void cp_commit() { asm volatile("cp.async.commit_group;"); }
template <int N> DEVFN void cp_wait() {
    asm volatile("cp.async.wait_group %0;" :: "n"(N));
}

DEVFN void ldsm4(uint32_t* r, uint32_t a) {
    asm volatile("ldmatrix.sync.aligned.m8n8.x4.shared.b16 {%0,%1,%2,%3}, [%4];"
                 : "=r"(r[0]), "=r"(r[1]), "=r"(r[2]), "=r"(r[3]) : "r"(a));
}

DEVFN void mma16816(float* d, const uint32_t* a, uint32_t b0, uint32_t b1) {
    asm volatile(
        "mma.sync.aligned.m16n8k16.row.col.f32.f16.f16.f32 "
        "{%0,%1,%2,%3}, {%4,%5,%6,%7}, {%8,%9}, {%0,%1,%2,%3};"
        : "+f"(d[0]), "+f"(d[1]), "+f"(d[2]), "+f"(d[3])
        : "r"(a[0]), "r"(a[1]), "r"(a[2]), "r"(a[3]), "r"(b0), "r"(b1));
}

DEVFN uint32_t pack2h(__half a, __half b) {
    return (uint32_t)__half_as_ushort(a) |
           ((uint32_t)__half_as_ushort(b) << 16);
}

DEVFN int ld_acq(const int* p) {
    int v;
    asm volatile("ld.global.acquire.gpu.b32 %0, [%1];" : "=r"(v) : "l"(p));
    return v;
}

// ---------------------------------------------------------------------------
// Packing kernels
// ---------------------------------------------------------------------------
__global__ void pack_x_kernel(const float4* __restrict__ x) {
    int idx = blockIdx.x * blockDim.x + threadIdx.x;   // over BATCH*N_IN/4
    if (idx < BATCH / 128) g_cnt[idx] = 0;             // reset dependency counters
    int m  = idx / (N_IN / 4);
    int k4 = idx % (N_IN / 4);
    float4 v = x[idx];
    uint2 u;
    u.x = pack2h(__float2half(v.x), __float2half(v.y));
    u.y = pack2h(__float2half(v.z), __float2half(v.w));
    *(uint2*)(g_A + (size_t)m * KA + k4 * 4) = u;
}

// out[n][k] = fp16(W[k][col0 + n]) — tiled transpose, coalesced 128B writes.
__global__ void pack_w_kernel(const float* __restrict__ W, int col0,
                              __half* __restrict__ outB, int pitchK) {
    __shared__ float t[64][33];
    int nb = blockIdx.x * 32, kb = blockIdx.y * 64;
    int tx = threadIdx.x, ty = threadIdx.y;   // (32, 8)
    #pragma unroll
    for (int i = 0; i < 8; i++) {
        int k = kb + ty + i * 8;
        t[ty + i * 8][tx] = W[(size_t)k * N_TOT + col0 + nb + tx];
    }
    __syncthreads();
    #pragma unroll
    for (int i = 0; i < 4; i++) {
        int n = nb + ty + i * 8;
        int k2 = tx * 2;              // pair of k within tile
        uint32_t u = pack2h(__float2half(t[k2][ty + i * 8]),
                            __float2half(t[k2 + 1][ty + i * 8]));
        *(uint32_t*)(outB + (size_t)n * pitchK + kb + k2) = u;
    }
}

// ---------------------------------------------------------------------------
// Fused network: one grid of 1024 GEMM1 tiles + 256 GEMM2 tiles.
// CTA tile 128x128, 128 threads (4 warps, 2x2, warp tile 64x64), 2 CTAs/SM.
//
//   bid <  1024 : GEMM1   hidden = relu(x @ W1) -> pack fp16 into g_A,
//                 then release-count its 128-row block.
//   bid >= 1024 : GEMM2   out = [x | hidden] @ W2, kc = 96. Runs chunks
//                 [0,32) (x-only) immediately — filling GEMM1's tail wave —
//                 and acquire-waits on its row block before prefetching
//                 chunk 32 (first hidden-dependent chunk).
// ---------------------------------------------------------------------------
static constexpr int BM = 128, BN = 128, BK = 64;
static constexpr int STAGES  = 3;
static constexpr int TILE_B  = BM * BK * 2;        // 16 KB
static constexpr int STAGE_B = 2 * TILE_B;         // A + B = 32 KB
static constexpr int SMEM_GEMM = STAGES * STAGE_B + 128;   // ~96 KB

static constexpr int G1_TILES = (BATCH / BM) * (N_HID / BN);  // 1024
static constexpr int G2_TILES = (BATCH / BM) * (N_OUT / BN);  // 256
static constexpr int G1_COLS  = N_HID / BN;                   // 32 tiles per row block

__global__ __launch_bounds__(128, 2)
void net_gemm(float* __restrict__ out)
{
    extern __shared__ char smraw[];
    uint32_t sb = (smem_u32(smraw) + 127u) & ~127u;

    const int tid  = threadIdx.x;
    const int wid  = tid >> 5;
    const int lane = tid & 31;
    const int bid  = blockIdx.x;

    // ---- mode resolve ----
    const __half *Abase, *Bbase;
    int ldA, ldB, kc, m0, n0, rowblk, kwait;
    bool is_g1;
    if (bid < G1_TILES) {                   // GEMM1
        is_g1 = true;
        rowblk = bid >> 5;
        m0 = rowblk * BM; n0 = (bid & 31) * BN;
        Abase = g_A;  ldA = KA;
        Bbase = g_B1; ldB = N_IN;
        kc = N_IN / BK;  kwait = 1 << 30;
    } else {                                // GEMM2 (full K)
        is_g1 = false;
        int t = bid - G1_TILES;
        rowblk = t >> 3;
        m0 = rowblk * BM; n0 = (t & 7) * BN;
        Abase = g_A;  ldA = KA;
        Bbase = g_B2; ldB = KA;
        kc = KA / BK;  kwait = N_IN / BK;   // wait before prefetching chunk 32
    }

    // ---- loader precompute: 128 threads, 16 rows per pass, 8 passes/tile ----
    const int c16 = tid & 7;          // 16B unit within 128B row
    const int rb  = tid >> 3;         // base row (0..15)
    const uint32_t lxor = (uint32_t)(rb & 7) << 4;
    const uint32_t srow0 = (uint32_t)rb * 128 + (((uint32_t)c16 * 16) ^ lxor);

    const __half* gA = Abase + (size_t)(m0 + rb) * ldA + c16 * 8;
    const __half* gB = Bbase + (size_t)(n0 + rb) * ldB + c16 * 8;

    auto load_stage = [&](int slot, int chunk) {
        uint32_t st = sb + slot * STAGE_B;
        int kcol = chunk * BK;
        #pragma unroll
        for (int j = 0; j < 8; j++) {
            cp16(st + srow0 + (uint32_t)(16 * j) * 128,
                 gA + (size_t)(16 * j) * ldA + kcol);
            cp16(st + TILE_B + srow0 + (uint32_t)(16 * j) * 128,
                 gB + (size_t)(16 * j) * ldB + kcol);
        }
    };

    // ---- fragment address precompute (manual swizzle) ----
    const int warp_m = wid >> 1;      // 0..1 : 64 rows
    const int warp_n = wid & 1;       // 0..1 : 64 cols
    const uint32_t aOff0 = (uint32_t)(warp_m * 64 + (lane & 15)) * 128;
    const uint32_t aKq   = ((uint32_t)lane >> 4) * 16;
    const uint32_t amask = ((uint32_t)lane & 7) << 4;
    const uint32_t bOff0 =
        (uint32_t)(warp_n * 64 + (lane & 7) + ((lane >> 4) << 3)) * 128;
    const uint32_t bKq   = (((uint32_t)lane >> 3) & 1) * 16;
    const uint32_t bmask = ((uint32_t)lane & 7) << 4;

    float acc[4][8][4];
    #pragma unroll
    for (int mt = 0; mt < 4; mt++)
        #pragma unroll
        for (int nt = 0; nt < 8; nt++)
            #pragma unroll
            for (int r = 0; r < 4; r++)
                acc[mt][nt][r] = 0.0f;

    // ---- pipeline prologue (chunks 0..2 are always x-range: no wait) ----
    int pro = kc < STAGES ? kc : STAGES;
    for (int i = 0; i < pro; i++) { load_stage(i, i); cp_commit(); }
    int issued = pro;

    // ---- mainloop ----
    int s = 0;
    for (int c = 0; c < kc; c++) {
        cp_wait<STAGES - 1>();
        __syncthreads();
        uint32_t st = sb + s * STAGE_B;

        #pragma unroll
        for (int ks = 0; ks < 4; ks++) {
            const uint32_t kb = ks * 32;
            uint32_t ah[4][4], bf[4][4];
            #pragma unroll
            for (int ng = 0; ng < 4; ng++)
                ldsm4(bf[ng], st + TILE_B + bOff0 + ng * 2048 + ((kb + bKq) ^ bmask));
            #pragma unroll
            for (int mt = 0; mt < 4; mt++)
                ldsm4(ah[mt], st + aOff0 + mt * 2048 + ((kb + aKq) ^ amask));

            #pragma unroll
            for (int mt = 0; mt < 4; mt++)
                #pragma unroll
                for (int nt = 0; nt < 8; nt++) {
                    const int ng = nt >> 1, hf = nt & 1;
                    mma16816(acc[mt][nt], ah[mt], bf[ng][hf * 2], bf[ng][hf * 2 + 1]);
                }
        }

        __syncthreads();
        if (issued < kc) {
            if (issued == kwait) {
                // first hidden-dependent chunk: wait for this row block's
                // 32 GEMM1 tiles to have released their results.
                if (tid == 0) {
                    while (ld_acq(&g_cnt[rowblk]) < G1_COLS) __nanosleep(128);
                }
                __syncthreads();
            }
            load_stage(s, issued); issued++;
        }
        cp_commit();
        if (++s == STAGES) s = 0;
    }

    // ---- epilogue ----
    const int gr  = lane >> 2;        // 0..7
    const int gc2 = (lane & 3) * 2;   // 0,2,4,6
    #pragma unroll
    for (int mt = 0; mt < 4; mt++)
        #pragma unroll
        for (int nt = 0; nt < 8; nt++)
            #pragma unroll
            for (int hf = 0; hf < 2; hf++) {   // hf=0: c0,c1 ; hf=1: c2,c3
                int row = m0 + warp_m * 64 + mt * 16 + gr + hf * 8;
                int col = n0 + warp_n * 64 + nt * 8 + gc2;
                float v0 = acc[mt][nt][hf * 2];
                float v1 = acc[mt][nt][hf * 2 + 1];
                if (is_g1) {
                    v0 = fmaxf(v0, 0.0f);
                    v1 = fmaxf(v1, 0.0f);
                    size_t o = (size_t)row * KA + N_IN + col;
                    *(uint32_t*)(g_A + o) =
                        pack2h(__float2half(v0), __float2half(v1));
                } else {
                    *(float2*)(out + (size_t)row * N_OUT + col) =
                        make_float2(v0, v1);
                }
            }

    // ---- GEMM1: release this tile's contribution ----
    if (is_g1) {
        __threadfence();          // order g_A stores (all threads)
        __syncthreads();
        if (tid == 0) atomicAdd(&g_cnt[rowblk], 1);
    }
}

// ---------------------------------------------------------------------------
// Host side
// ---------------------------------------------------------------------------
extern "C" void kernel_launch(void* const* d_in, const int* in_sizes, int n_in,
                              void* d_out, int out_size)
{
    const float* x = (const float*)d_in[0];        // (4096, 2048)
    const float* W = (const float*)d_in[1];        // (7168, 7168)
    float* out = (float*)d_out;                    // (4096, 1024)

    void *pB1, *pB2;
    cudaGetSymbolAddress(&pB1, g_B1);
    cudaGetSymbolAddress(&pB2, g_B2);

    cudaFuncSetAttribute(net_gemm,
        cudaFuncAttributeMaxDynamicSharedMemorySize, SMEM_GEMM);

    // 1) pack x into A cols [0, 2048) and reset counters
    pack_x_kernel<<<(BATCH * N_IN / 4) / 256, 256>>>((const float4*)x);

    // 2) transpose W slices to fp16 K-major
    pack_w_kernel<<<dim3(N_HID / 32, N_IN / 64), dim3(32, 8)>>>(
        W, N_IN, (__half*)pB1, N_IN);
    pack_w_kernel<<<dim3(N_OUT / 32, KA / 64), dim3(32, 8)>>>(
        W, N_IN + N_HID, (__half*)pB2, KA);

    // 3) fused GEMM1 + GEMM2 (dependency via per-rowblock counters)
    net_gemm<<<G1_TILES + G2_TILES, 128, SMEM_GEMM>>>(out);
}

// round 11
// speedup vs baseline: 1.2209x; 1.0079x over previous
#include <cuda_runtime.h>
#include <cuda_fp16.h>
#include <cstdint>
#include <cstddef>

// ---------------------------------------------------------------------------
// Problem dims
// ---------------------------------------------------------------------------
static constexpr int N_IN  = 2048;
static constexpr int N_HID = 4096;
static constexpr int N_OUT = 1024;
static constexpr int N_TOT = 7168;
static constexpr int BATCH = 4096;
static constexpr int KA    = N_IN + N_HID;   // 6144 : packed A = [x | hidden]

// ---------------------------------------------------------------------------
// Device scratch (allocation-free rule: __device__ globals)
// ---------------------------------------------------------------------------
__device__ __align__(1024) __half g_A[(size_t)BATCH * KA];       // [x | hidden] fp16
__device__ __align__(1024) __half g_B1[(size_t)N_HID * N_IN];    // W1^T fp16
__device__ __align__(1024) __half g_B2[(size_t)N_OUT * KA];      // W2^T fp16
__device__ int g_cnt[BATCH / 128];   // per 128-row block: # finished GEMM1 tiles

#define DEVFN __device__ __forceinline__

DEVFN uint32_t smem_u32(const void* p) {
    uint32_t a;
    asm("{ .reg .u64 t; cvta.to.shared.u64 t, %1; cvt.u32.u64 %0, t; }"
        : "=r"(a) : "l"(p));
    return a;
}

DEVFN void cp16(uint32_t s, const void* g) {
    asm volatile("cp.async.cg.shared.global [%0], [%1], 16;"
                 :: "r"(s), "l"(g));
}
DEVFN void cp_commit() { asm volatile("cp.async.commit_group;"); }
template <int N> DEVFN void cp_wait() {
    asm volatile("cp.async.wait_group %0;" :: "n"(N));
}

DEVFN void ldsm4(uint32_t* r, uint32_t a) {
    asm volatile("ldmatrix.sync.aligned.m8n8.x4.shared.b16 {%0,%1,%2,%3}, [%4];"
                 : "=r"(r[0]), "=r"(r[1]), "=r"(r[2]), "=r"(r[3]) : "r"(a));
}

DEVFN void mma16816(float* d, const uint32_t* a, uint32_t b0, uint32_t b1) {
    asm volatile(
        "mma.sync.aligned.m16n8k16.row.col.f32.f16.f16.f32 "
        "{%0,%1,%2,%3}, {%4,%5,%6,%7}, {%8,%9}, {%0,%1,%2,%3};"
        : "+f"(d[0]), "+f"(d[1]), "+f"(d[2]), "+f"(d[3])
        : "r"(a[0]), "r"(a[1]), "r"(a[2]), "r"(a[3]), "r"(b0), "r"(b1));
}

DEVFN uint32_t pack2h(__half a, __half b) {
    return (uint32_t)__half_as_ushort(a) |
           ((uint32_t)__half_as_ushort(b) << 16);
}

DEVFN int ld_acq(const int* p) {
    int v;
    asm volatile("ld.global.acquire.gpu.b32 %0, [%1];" : "=r"(v) : "l"(p));
    return v;
}

// ---------------------------------------------------------------------------
// Fused packing kernel: one launch does x-pack + W1 transpose + W2 transpose.
//   blocks [0, PX)            : pack x rows into g_A cols [0, N_IN)
//   blocks [PX, PX+PW1)       : W1^T slice  (k64 x n32 transpose tiles)
//   blocks [PX+PW1, ...+PW2)  : W2^T slice
// 256 threads per block.
// ---------------------------------------------------------------------------
static constexpr int PX_BLK  = (BATCH * (N_IN / 4)) / 256;            // 8192
static constexpr int W1_NB   = N_HID / 32, W1_KB = N_IN / 64;         // 128, 32
static constexpr int W2_NB   = N_OUT / 32, W2_KB = KA / 64;           // 32, 96
static constexpr int PW1_BLK = W1_NB * W1_KB;                         // 4096
static constexpr int PW2_BLK = W2_NB * W2_KB;                         // 3072

__global__ void pack_all(const float4* __restrict__ x,
                         const float* __restrict__ W) {
    __shared__ float t[64][33];
    const int bid = blockIdx.x;
    const int tid = threadIdx.x;

    if (bid < PX_BLK) {
        int idx = bid * 256 + tid;
        if (idx < BATCH / 128) g_cnt[idx] = 0;      // reset dependency counters
        int m  = idx / (N_IN / 4);
        int k4 = idx % (N_IN / 4);
        float4 v = x[idx];
        uint2 u;
        u.x = pack2h(__float2half(v.x), __float2half(v.y));
        u.y = pack2h(__float2half(v.z), __float2half(v.w));
        *(uint2*)(g_A + (size_t)m * KA + k4 * 4) = u;
        return;
    }

    // ---- W transpose tiles ----
    int col0, pitchK, nb, kb;
    __half* outB;
    if (bid < PX_BLK + PW1_BLK) {
        int b = bid - PX_BLK;
        col0 = N_IN; pitchK = N_IN; outB = g_B1;
        nb = (b % W1_NB) * 32; kb = (b / W1_NB) * 64;
    } else {
        int b = bid - PX_BLK - PW1_BLK;
        col0 = N_IN + N_HID; pitchK = KA; outB = g_B2;
        nb = (b % W2_NB) * 32; kb = (b / W2_NB) * 64;
    }
    int tx = tid & 31, ty = tid >> 5;   // (32, 8)
    #pragma unroll
    for (int i = 0; i < 8; i++) {
        int k = kb + ty + i * 8;
        t[ty + i * 8][tx] = W[(size_t)k * N_TOT + col0 + nb + tx];
    }
    __syncthreads();
    #pragma unroll
    for (int i = 0; i < 4; i++) {
        int n = nb + ty + i * 8;
        int k2 = tx * 2;
        uint32_t u = pack2h(__float2half(t[k2][ty + i * 8]),
                            __float2half(t[k2 + 1][ty + i * 8]));
        *(uint32_t*)(outB + (size_t)n * pitchK + kb + k2) = u;
    }
}

// ---------------------------------------------------------------------------
// Fused network: one grid of 1024 GEMM1 tiles + 256 GEMM2 tiles.
// CTA tile 128x128, 128 threads (4 warps, 2x2, warp tile 64x64), 2 CTAs/SM.
// Single-sync software pipeline: prologue 2 chunks, wait<1>, loads at top.
// ---------------------------------------------------------------------------
static constexpr int BM = 128, BN = 128, BK = 64;
static constexpr int STAGES  = 3;
static constexpr int TILE_B  = BM * BK * 2;        // 16 KB
static constexpr int STAGE_B = 2 * TILE_B;         // A + B = 32 KB
static constexpr int SMEM_GEMM = STAGES * STAGE_B + 128;   // ~96 KB

static constexpr int G1_TILES = (BATCH / BM) * (N_HID / BN);  // 1024
static constexpr int G2_TILES = (BATCH / BM) * (N_OUT / BN);  // 256
static constexpr int G1_COLS  = N_HID / BN;                   // 32 tiles per row block

__global__ __launch_bounds__(128, 2)
void net_gemm(float* __restrict__ out)
{
    extern __shared__ char smraw[];
    uint32_t sb = (smem_u32(smraw) + 127u) & ~127u;

    const int tid  = threadIdx.x;
    const int wid  = tid >> 5;
    const int lane = tid & 31;
    const int bid  = blockIdx.x;

    // ---- mode resolve ----
    const __half *Abase, *Bbase;
    int ldA, ldB, kc, m0, n0, rowblk, kwait;
    bool is_g1;
    if (bid < G1_TILES) {                   // GEMM1
        is_g1 = true;
        rowblk = bid >> 5;
        m0 = rowblk * BM; n0 = (bid & 31) * BN;
        Abase = g_A;  ldA = KA;
        Bbase = g_B1; ldB = N_IN;
        kc = N_IN / BK;  kwait = 1 << 30;
    } else {                                // GEMM2 (full K)
        is_g1 = false;
        int t = bid - G1_TILES;
        rowblk = t >> 3;
        m0 = rowblk * BM; n0 = (t & 7) * BN;
        Abase = g_A;  ldA = KA;
        Bbase = g_B2; ldB = KA;
        kc = KA / BK;  kwait = N_IN / BK;   // wait before loading chunk 32
    }

    // ---- loader precompute: 128 threads, 16 rows per pass, 8 passes/tile ----
    const int c16 = tid & 7;          // 16B unit within 128B row
    const int rb  = tid >> 3;         // base row (0..15)
    const uint32_t lxor = (uint32_t)(rb & 7) << 4;
    const uint32_t srow0 = (uint32_t)rb * 128 + (((uint32_t)c16 * 16) ^ lxor);

    const __half* gA = Abase + (size_t)(m0 + rb) * ldA + c16 * 8;
    const __half* gB = Bbase + (size_t)(n0 + rb) * ldB + c16 * 8;

    auto load_stage = [&](int slot, int chunk) {
        uint32_t st = sb + slot * STAGE_B;
        int kcol = chunk * BK;
        #pragma unroll
        for (int j = 0; j < 8; j++) {
            cp16(st + srow0 + (uint32_t)(16 * j) * 128,
                 gA + (size_t)(16 * j) * ldA + kcol);
            cp16(st + TILE_B + srow0 + (uint32_t)(16 * j) * 128,
                 gB + (size_t)(16 * j) * ldB + kcol);
        }
    };

    // ---- fragment address precompute (manual swizzle) ----
    const int warp_m = wid >> 1;      // 0..1 : 64 rows
    const int warp_n = wid & 1;       // 0..1 : 64 cols
    const uint32_t aOff0 = (uint32_t)(warp_m * 64 + (lane & 15)) * 128;
    const uint32_t aKq   = ((uint32_t)lane >> 4) * 16;
    const uint32_t amask = ((uint32_t)lane & 7) << 4;
    const uint32_t bOff0 =
        (uint32_t)(warp_n * 64 + (lane & 7) + ((lane >> 4) << 3)) * 128;
    const uint32_t bKq   = (((uint32_t)lane >> 3) & 1) * 16;
    const uint32_t bmask = ((uint32_t)lane & 7) << 4;

    float acc[4][8][4];
    #pragma unroll
    for (int mt = 0; mt < 4; mt++)
        #pragma unroll
        for (int nt = 0; nt < 8; nt++)
            #pragma unroll
            for (int r = 0; r < 4; r++)
                acc[mt][nt][r] = 0.0f;

    // ---- pipeline prologue: STAGES-1 = 2 chunks in flight ----
    #pragma unroll
    for (int i = 0; i < STAGES - 1; i++) { load_stage(i, i); cp_commit(); }
    int issued = STAGES - 1;

    // ---- single-sync mainloop ----
    int s = 0;
    for (int c = 0; c < kc; c++) {
        cp_wait<STAGES - 2>();     // chunk c resident
        __syncthreads();           // all warps done reading the slot loaded next

        int ns = s + (STAGES - 1); if (ns >= STAGES) ns -= STAGES;
        if (issued < kc) {
            if (issued == kwait) {
                // first hidden-dependent chunk: wait for this row block's
                // GEMM1 tiles to have released their results.
                if (tid == 0) {
                    while (ld_acq(&g_cnt[rowblk]) < G1_COLS) __nanosleep(128);
                }
                __syncthreads();
            }
            load_stage(ns, issued); issued++;
        }
        cp_commit();               // commit every iter (empty ok) for wait count

        uint32_t st = sb + s * STAGE_B;
        #pragma unroll
        for (int ks = 0; ks < 4; ks++) {
            const uint32_t kb = ks * 32;
            uint32_t ah[4][4], bf[4][4];
            #pragma unroll
            for (int ng = 0; ng < 4; ng++)
                ldsm4(bf[ng], st + TILE_B + bOff0 + ng * 2048 + ((kb + bKq) ^ bmask));
            #pragma unroll
            for (int mt = 0; mt < 4; mt++)
                ldsm4(ah[mt], st + aOff0 + mt * 2048 + ((kb + aKq) ^ amask));

            #pragma unroll
            for (int mt = 0; mt < 4; mt++)
                #pragma unroll
                for (int nt = 0; nt < 8; nt++) {
                    const int ng = nt >> 1, hf = nt & 1;
                    mma16816(acc[mt][nt], ah[mt], bf[ng][hf * 2], bf[ng][hf * 2 + 1]);
                }
        }

        if (++s == STAGES) s = 0;
    }

    // ---- epilogue ----
    const int gr  = lane >> 2;        // 0..7
    const int gc2 = (lane & 3) * 2;   // 0,2,4,6
    #pragma unroll
    for (int mt = 0; mt < 4; mt++)
        #pragma unroll
        for (int nt = 0; nt < 8; nt++)
            #pragma unroll
            for (int hf = 0; hf < 2; hf++) {   // hf=0: c0,c1 ; hf=1: c2,c3
                int row = m0 + warp_m * 64 + mt * 16 + gr + hf * 8;
                int col = n0 + warp_n * 64 + nt * 8 + gc2;
                float v0 = acc[mt][nt][hf * 2];
                float v1 = acc[mt][nt][hf * 2 + 1];
                if (is_g1) {
                    v0 = fmaxf(v0, 0.0f);
                    v1 = fmaxf(v1, 0.0f);
                    size_t o = (size_t)row * KA + N_IN + col;
                    *(uint32_t*)(g_A + o) =
                        pack2h(__float2half(v0), __float2half(v1));
                } else {
                    *(float2*)(out + (size_t)row * N_OUT + col) =
                        make_float2(v0, v1);
                }
            }

    // ---- GEMM1: release this tile's contribution ----
    if (is_g1) {
        __threadfence();          // order g_A stores (all threads)
        __syncthreads();
        if (tid == 0) atomicAdd(&g_cnt[rowblk], 1);
    }
}

// ---------------------------------------------------------------------------
// Host side
// ---------------------------------------------------------------------------
extern "C" void kernel_launch(void* const* d_in, const int* in_sizes, int n_in,
                              void* d_out, int out_size)
{
    const float* x = (const float*)d_in[0];        // (4096, 2048)
    const float* W = (const float*)d_in[1];        // (7168, 7168)
    float* out = (float*)d_out;                    // (4096, 1024)

    cudaFuncSetAttribute(net_gemm,
        cudaFuncAttributeMaxDynamicSharedMemorySize, SMEM_GEMM);

    // 1) fused packing: x -> g_A, W1^T -> g_B1, W2^T -> g_B2, counters reset
    pack_all<<<PX_BLK + PW1_BLK + PW2_BLK, 256>>>((const float4*)x, W);

    // 2) fused GEMM1 + GEMM2 (dependency via per-rowblock counters)
    net_gemm<<<G1_TILES + G2_TILES, 128, SMEM_GEMM>>>(out);
}